// round 11
// baseline (speedup 1.0000x reference)
#include <cuda_runtime.h>
#include <math.h>

#define B_  512
#define T_  512
#define H_  100
#define DI_ 101
#define DO_ 2

typedef unsigned long long ull;

__device__ float g_xp[(size_t)B_ * T_ * H_];   // holds 0.1*(inp@Wx^T + b)

__device__ __forceinline__ ull fma2(ull a, ull b, ull c) {
    ull d;
    asm("fma.rn.f32x2 %0, %1, %2, %3;" : "=l"(d) : "l"(a), "l"(b), "l"(c));
    return d;
}
__device__ __forceinline__ ull add2(ull a, ull b) {
    ull d;
    asm("add.rn.f32x2 %0, %1, %2;" : "=l"(d) : "l"(a), "l"(b));
    return d;
}
__device__ __forceinline__ ull dup2(float a) {
    ull d;
    asm("mov.b64 %0, {%1, %1};" : "=l"(d) : "f"(a));
    return d;
}
__device__ __forceinline__ float2 u2f(ull v) {
    float2 f;
    asm("mov.b64 {%0, %1}, %2;" : "=f"(f.x), "=f"(f.y) : "l"(v));
    return f;
}
__device__ __forceinline__ void cp_async4(unsigned smem_addr, const void* gptr) {
    asm volatile("cp.async.ca.shared.global [%0], [%1], 4;"
                 :: "r"(smem_addr), "l"(gptr));
}

// ---------------------------------------------------------------------------
// Kernel A: g_xp[r][j] = 0.1*(sum_i input[r][i]*Wx[j][i] + b[j])
// 128 threads, 64-row tiles, 16x4 microtile per warp (rows FFMA2-packed).
// ---------------------------------------------------------------------------
#define INS_STRIDE 68
__global__ void __launch_bounds__(128, 3) xp_gemm_kernel(
    const float* __restrict__ inp,   // [B*T, DI]
    const float* __restrict__ Wx,    // [H, DI]
    const float* __restrict__ bias)  // [H]
{
    extern __shared__ __align__(16) float smem[];
    float* Wx_s = smem;                 // [i][j]  (pre-scaled by 0.1)
    float* in_s = smem + DI_ * H_;      // [i][r]

    const int tid = threadIdx.x;
    const int tx  = tid & 31;   // col quad (active tx < 25)
    const int ty  = tid >> 5;   // warp id (0..3) -> rows 16*ty..16*ty+15

    for (int idx = tid; idx < DI_ * H_; idx += 128) {
        int j = idx / DI_;
        int i = idx - j * DI_;
        Wx_s[i * H_ + j] = 0.1f * Wx[idx];
    }

    float bv[4] = {0.f, 0.f, 0.f, 0.f};
    if (tx < 25) {
#pragma unroll
        for (int c = 0; c < 4; c++) bv[c] = 0.1f * bias[4 * tx + c];
    }

    int r0 = 0, i0 = tid;
    if (i0 >= DI_) { i0 -= DI_; r0 += 1; }

    const int ntiles = (B_ * T_) / 64;   // 4096
    for (int tile = blockIdx.x; tile < ntiles; tile += gridDim.x) {
        __syncthreads();
        const size_t gbase = (size_t)tile * 64 * DI_;
        {
            int r = r0, i = i0, idx = tid;
#pragma unroll 4
            for (int it = 0; it < 51; it++) {
                if (idx < 64 * DI_) in_s[i * INS_STRIDE + r] = inp[gbase + idx];
                idx += 128;
                i += 27; r += 1;                 // 128 = 101 + 27
                if (i >= DI_) { i -= DI_; r += 1; }
            }
        }
        __syncthreads();

        if (tx < 25) {
            ull acc[8][4];
#pragma unroll
            for (int p = 0; p < 8; p++)
#pragma unroll
                for (int c = 0; c < 4; c++) acc[p][c] = dup2(bv[c]);

#pragma unroll 2
            for (int i = 0; i < DI_; i++) {
                const float* ib = in_s + i * INS_STRIDE + 16 * ty;
                ulonglong2 ap0 = *(const ulonglong2*)(ib);
                ulonglong2 ap1 = *(const ulonglong2*)(ib + 4);
                ulonglong2 ap2 = *(const ulonglong2*)(ib + 8);
                ulonglong2 ap3 = *(const ulonglong2*)(ib + 12);
                float4 wv = *(const float4*)(Wx_s + i * H_ + 4 * tx);
                ull w0 = dup2(wv.x), w1 = dup2(wv.y), w2 = dup2(wv.z), w3 = dup2(wv.w);
                acc[0][0] = fma2(ap0.x, w0, acc[0][0]);
                acc[0][1] = fma2(ap0.x, w1, acc[0][1]);
                acc[0][2] = fma2(ap0.x, w2, acc[0][2]);
                acc[0][3] = fma2(ap0.x, w3, acc[0][3]);
                acc[1][0] = fma2(ap0.y, w0, acc[1][0]);
                acc[1][1] = fma2(ap0.y, w1, acc[1][1]);
                acc[1][2] = fma2(ap0.y, w2, acc[1][2]);
                acc[1][3] = fma2(ap0.y, w3, acc[1][3]);
                acc[2][0] = fma2(ap1.x, w0, acc[2][0]);
                acc[2][1] = fma2(ap1.x, w1, acc[2][1]);
                acc[2][2] = fma2(ap1.x, w2, acc[2][2]);
                acc[2][3] = fma2(ap1.x, w3, acc[2][3]);
                acc[3][0] = fma2(ap1.y, w0, acc[3][0]);
                acc[3][1] = fma2(ap1.y, w1, acc[3][1]);
                acc[3][2] = fma2(ap1.y, w2, acc[3][2]);
                acc[3][3] = fma2(ap1.y, w3, acc[3][3]);
                acc[4][0] = fma2(ap2.x, w0, acc[4][0]);
                acc[4][1] = fma2(ap2.x, w1, acc[4][1]);
                acc[4][2] = fma2(ap2.x, w2, acc[4][2]);
                acc[4][3] = fma2(ap2.x, w3, acc[4][3]);
                acc[5][0] = fma2(ap2.y, w0, acc[5][0]);
                acc[5][1] = fma2(ap2.y, w1, acc[5][1]);
                acc[5][2] = fma2(ap2.y, w2, acc[5][2]);
                acc[5][3] = fma2(ap2.y, w3, acc[5][3]);
                acc[6][0] = fma2(ap3.x, w0, acc[6][0]);
                acc[6][1] = fma2(ap3.x, w1, acc[6][1]);
                acc[6][2] = fma2(ap3.x, w2, acc[6][2]);
                acc[6][3] = fma2(ap3.x, w3, acc[6][3]);
                acc[7][0] = fma2(ap3.y, w0, acc[7][0]);
                acc[7][1] = fma2(ap3.y, w1, acc[7][1]);
                acc[7][2] = fma2(ap3.y, w2, acc[7][2]);
                acc[7][3] = fma2(ap3.y, w3, acc[7][3]);
            }
            const int rbase = tile * 64 + 16 * ty;
#pragma unroll
            for (int p = 0; p < 8; p++) {
                float2 c0 = u2f(acc[p][0]);
                float2 c1 = u2f(acc[p][1]);
                float2 c2 = u2f(acc[p][2]);
                float2 c3 = u2f(acc[p][3]);
                int re = rbase + 2 * p;
                float4 oe; oe.x = c0.x; oe.y = c1.x; oe.z = c2.x; oe.w = c3.x;
                float4 oo; oo.x = c0.y; oo.y = c1.y; oo.z = c2.y; oo.w = c3.y;
                *(float4*)(g_xp + (size_t)re * H_ + 4 * tx)       = oe;
                *(float4*)(g_xp + (size_t)(re + 1) * H_ + 4 * tx) = oo;
            }
        }
    }
}

// ---------------------------------------------------------------------------
// Kernel B: sequential scan, CHAIN-PACKED (FIXED k-loop: 50 x ulonglong2
// covers all 100 k; round-10 bug was 25). 256 CTAs x 128 threads, occ 2,
// 2 chains/CTA. Thread j owns row j for both chains; wkd[100] duplicated
// scaled weights (~200 regs, fits occ-2 cap 256). h as float2[k]=(c0,c1);
// fma2 packs over the chain dim. Tail (tanh/stores/barrier) amortized over
// 2 chains. xp/noise via depth-4 cp.async ring.
// ---------------------------------------------------------------------------
__global__ void __launch_bounds__(128, 2) scan_kernel(
    const float* __restrict__ noise,   // [B, T, H]
    const float* __restrict__ Wh,      // [H, H]
    const float* __restrict__ ah0,     // [H]
    float* __restrict__ hstore)        // [B, T, H]
{
    __shared__ __align__(16) float2 hs[2][112];    // [buf][k] -> (h_c0, h_c1)
    __shared__ __align__(16) float2 rxp[4][112];   // [slot][j] -> (xp_c0, xp_c1)
    __shared__ __align__(16) float2 rnz[4][112];

    const int tid  = threadIdx.x;
    const int lane = tid & 31;
    const int w    = tid >> 5;
    const int j    = 25 * w + lane;
    const bool act = lane < 25;
    const int c0   = blockIdx.x * 2;

    // de-phase co-resident CTAs
    {
        long long lim = (long long)((blockIdx.x & 1) * 300);
        long long s0 = clock64();
        while (clock64() - s0 < lim) {}
    }

    // duplicated scaled weights: wkd[k] = (0.1*W[j][k], 0.1*W[j][k])
    ull wkd[100];
    if (act) {
        const float4* wr = (const float4*)(Wh + j * H_);
#pragma unroll
        for (int q = 0; q < 25; q++) {
            float4 v = wr[q];
            wkd[4 * q + 0] = dup2(0.1f * v.x);
            wkd[4 * q + 1] = dup2(0.1f * v.y);
            wkd[4 * q + 2] = dup2(0.1f * v.z);
            wkd[4 * q + 3] = dup2(0.1f * v.w);
        }
    }

    ull ahp = 0;
    if (act) {
        float a0 = ah0[j];
        ahp = dup2(a0);
        float h0 = tanhf(fmaxf(a0, 0.f));
        hs[0][j] = make_float2(h0, h0);
    }

    const float* xpA = g_xp  + (size_t)(c0 + 0) * (T_ * H_) + j;
    const float* xpB = g_xp  + (size_t)(c0 + 1) * (T_ * H_) + j;
    const float* nzA = noise + (size_t)(c0 + 0) * (T_ * H_) + j;
    const float* nzB = noise + (size_t)(c0 + 1) * (T_ * H_) + j;
    float* hstA = hstore + (size_t)(c0 + 0) * (T_ * H_) + j;
    float* hstB = hstore + (size_t)(c0 + 1) * (T_ * H_) + j;

    unsigned rxp_a = (unsigned)__cvta_generic_to_shared(rxp);
    unsigned rnz_a = (unsigned)__cvta_generic_to_shared(rnz);

#pragma unroll
    for (int p = 0; p < 3; p++) {
        if (act) {
            unsigned eo = 8u * (p * 112 + j);
            cp_async4(rxp_a + eo,     xpA + (size_t)p * H_);
            cp_async4(rxp_a + eo + 4, xpB + (size_t)p * H_);
            cp_async4(rnz_a + eo,     nzA + (size_t)p * H_);
            cp_async4(rnz_a + eo + 4, nzB + (size_t)p * H_);
        }
        asm volatile("cp.async.commit_group;");
    }
    __syncthreads();

    const ull c09 = dup2(0.9f);
    int buf = 0;
    for (int t = 0; t < T_; t++) {
        if (act && t + 3 < T_) {
            int s = (t + 3) & 3;
            unsigned eo = 8u * (s * 112 + j);
            cp_async4(rxp_a + eo,     xpA + (size_t)(t + 3) * H_);
            cp_async4(rxp_a + eo + 4, xpB + (size_t)(t + 3) * H_);
            cp_async4(rnz_a + eo,     nzA + (size_t)(t + 3) * H_);
            cp_async4(rnz_a + eo + 4, nzB + (size_t)(t + 3) * H_);
        }
        asm volatile("cp.async.commit_group;");
        asm volatile("cp.async.wait_group 3;");   // slot t complete

        if (act) {
            const ulonglong2* hp = (const ulonglong2*)hs[buf];
            ull a = 0, b = 0;
#pragma unroll
            for (int i = 0; i < 50; i++) {        // FIXED: 50 iters cover k=0..99
                ulonglong2 v = hp[i];             // v.x=(c0,c1)@k=2i, v.y=@k=2i+1
                a = fma2(v.x, wkd[2 * i],     a);
                b = fma2(v.y, wkd[2 * i + 1], b);
            }
            ull accp = add2(a, b);                // (0.1*(W h)_j for c0, c1)

            ull xu = *(const ull*)&rxp[t & 3][j];
            float2 nv = rnz[t & 3][j];
            ahp = fma2(c09, ahp, add2(accp, xu));

            float2 av = u2f(ahp);
            float xA = fmaxf(av.x, 0.f);
            float xB = fmaxf(av.y, 0.f);
            float eA = __expf(-2.f * xA);
            float eB = __expf(-2.f * xB);
            float hA = __fdividef(1.f - eA, 1.f + eA) + nv.x;
            float hB = __fdividef(1.f - eB, 1.f + eB) + nv.y;

            hs[buf ^ 1][j] = make_float2(hA, hB);
            hstA[(size_t)t * H_] = hA;
            hstB[(size_t)t * H_] = hB;
        }
        buf ^= 1;
        __syncthreads();
    }
}

// ---------------------------------------------------------------------------
// Kernel C: output[r][d] = sum_j hstore[r][j] * W_y[d][j]
// ---------------------------------------------------------------------------
__global__ void __launch_bounds__(256) outproj_kernel(
    const float* __restrict__ hst,   // [B*T, H]
    const float* __restrict__ Wy,    // [DO, H]
    float* __restrict__ out)         // [B*T, DO]
{
    __shared__ float wy_s[DO_ * H_];
    const int tid = threadIdx.x;
    for (int idx = tid; idx < DO_ * H_; idx += 256) wy_s[idx] = Wy[idx];
    __syncthreads();

    const int lane = tid & 31;
    const int w    = tid >> 5;
    const size_t row = (size_t)blockIdx.x * 8 + w;

    float a0 = 0.f, a1 = 0.f;
    for (int j = lane; j < H_; j += 32) {
        float h = hst[row * H_ + j];
        a0 = fmaf(h, wy_s[j],      a0);
        a1 = fmaf(h, wy_s[H_ + j], a1);
    }
#pragma unroll
    for (int off = 16; off > 0; off >>= 1) {
        a0 += __shfl_down_sync(0xffffffffu, a0, off);
        a1 += __shfl_down_sync(0xffffffffu, a1, off);
    }
    if (lane == 0) {
        out[row * DO_ + 0] = a0;
        out[row * DO_ + 1] = a1;
    }
}

// ---------------------------------------------------------------------------
extern "C" void kernel_launch(void* const* d_in, const int* in_sizes, int n_in,
                              void* d_out, int out_size)
{
    const float* inp   = (const float*)d_in[0];  // [B,T,DI]
    const float* noise = (const float*)d_in[1];  // [B,T,H]
    const float* Wx    = (const float*)d_in[2];  // [H,DI]
    const float* bias  = (const float*)d_in[3];  // [H]
    const float* Wh    = (const float*)d_in[4];  // [H,H]
    const float* Wy    = (const float*)d_in[5];  // [DO,H]
    const float* ah0   = (const float*)d_in[6];  // [H]

    float* out    = (float*)d_out;                  // [B,T,DO] first
    float* hstore = out + (size_t)B_ * T_ * DO_;    // [B,T,H] second

    const int xp_smem = (DI_ * H_ + DI_ * INS_STRIDE) * (int)sizeof(float);  // 67872 B
    static int attr_done = 0;
    if (!attr_done) {
        cudaFuncSetAttribute(xp_gemm_kernel,
                             cudaFuncAttributeMaxDynamicSharedMemorySize, xp_smem);
        cudaFuncSetAttribute(xp_gemm_kernel,
                             cudaFuncAttributePreferredSharedMemoryCarveout,
                             cudaSharedmemCarveoutMaxShared);
        attr_done = 1;
    }

    xp_gemm_kernel<<<1024, 128, xp_smem>>>(inp, Wx, bias);
    scan_kernel<<<B_ / 2, 128>>>(noise, Wh, ah0, hstore);
    outproj_kernel<<<(B_ * T_) / 8, 256>>>(hstore, Wy, out);
}

// round 12
// speedup vs baseline: 1.0271x; 1.0271x over previous
#include <cuda_runtime.h>
#include <math.h>

#define B_  512
#define T_  512
#define H_  100
#define DI_ 101
#define DO_ 2

typedef unsigned long long ull;

__device__ float g_xp[(size_t)B_ * T_ * H_];   // holds 0.1*(inp@Wx^T + b)

__device__ __forceinline__ ull fma2(ull a, ull b, ull c) {
    ull d;
    asm("fma.rn.f32x2 %0, %1, %2, %3;" : "=l"(d) : "l"(a), "l"(b), "l"(c));
    return d;
}
__device__ __forceinline__ ull add2(ull a, ull b) {
    ull d;
    asm("add.rn.f32x2 %0, %1, %2;" : "=l"(d) : "l"(a), "l"(b));
    return d;
}
__device__ __forceinline__ ull dup2(float a) {
    ull d;
    asm("mov.b64 %0, {%1, %1};" : "=l"(d) : "f"(a));
    return d;
}
__device__ __forceinline__ ull pack2(float lo, float hi) {
    ull d;
    asm("mov.b64 %0, {%1, %2};" : "=l"(d) : "f"(lo), "f"(hi));
    return d;
}
__device__ __forceinline__ float2 u2f(ull v) {
    float2 f;
    asm("mov.b64 {%0, %1}, %2;" : "=f"(f.x), "=f"(f.y) : "l"(v));
    return f;
}

// ---------------------------------------------------------------------------
// Kernel A: g_xp[r][j] = 0.1*(sum_i input[r][i]*Wx[j][i] + b[j])
// EXACT round-7 kernel (measured 163.9us): 256 threads, 64-row tiles,
// 8x4 microtile rows-FFMA2-packed, INS_STRIDE 68, occ-3 carveout.
// ---------------------------------------------------------------------------
#define INS_STRIDE 68
__global__ void __launch_bounds__(256, 3) xp_gemm_kernel(
    const float* __restrict__ inp,   // [B*T, DI]
    const float* __restrict__ Wx,    // [H, DI]
    const float* __restrict__ bias)  // [H]
{
    extern __shared__ __align__(16) float smem[];
    float* Wx_s = smem;                 // [i][j]  (pre-scaled by 0.1)
    float* in_s = smem + DI_ * H_;      // [i][r]

    const int tid = threadIdx.x;
    const int tx  = tid & 31;   // col quad (active tx < 25)
    const int ty  = tid >> 5;   // warp id (0..7) -> rows 8*ty..8*ty+7

    for (int idx = tid; idx < DI_ * H_; idx += 256) {
        int j = idx / DI_;
        int i = idx - j * DI_;
        Wx_s[i * H_ + j] = 0.1f * Wx[idx];
    }

    float bv[4] = {0.f, 0.f, 0.f, 0.f};
    if (tx < 25) {
#pragma unroll
        for (int c = 0; c < 4; c++) bv[c] = 0.1f * bias[4 * tx + c];
    }

    const int ntiles = (B_ * T_) / 64;   // 4096
    for (int tile = blockIdx.x; tile < ntiles; tile += gridDim.x) {
        __syncthreads();
        const int rbase = tile * 64;
        for (int idx = tid; idx < 64 * DI_; idx += 256) {
            int r = idx / DI_;
            int i = idx - r * DI_;
            in_s[i * INS_STRIDE + r] = inp[(size_t)(rbase + r) * DI_ + i];
        }
        __syncthreads();

        if (tx < 25) {
            ull acc[4][4];
#pragma unroll
            for (int p = 0; p < 4; p++)
#pragma unroll
                for (int c = 0; c < 4; c++) acc[p][c] = dup2(bv[c]);

#pragma unroll 4
            for (int i = 0; i < DI_; i++) {
                ulonglong2 ap0 = *(const ulonglong2*)(in_s + i * INS_STRIDE + 8 * ty);
                ulonglong2 ap1 = *(const ulonglong2*)(in_s + i * INS_STRIDE + 8 * ty + 4);
                float4 wv = *(const float4*)(Wx_s + i * H_ + 4 * tx);
                ull w0 = dup2(wv.x), w1 = dup2(wv.y), w2 = dup2(wv.z), w3 = dup2(wv.w);
                acc[0][0] = fma2(ap0.x, w0, acc[0][0]);
                acc[0][1] = fma2(ap0.x, w1, acc[0][1]);
                acc[0][2] = fma2(ap0.x, w2, acc[0][2]);
                acc[0][3] = fma2(ap0.x, w3, acc[0][3]);
                acc[1][0] = fma2(ap0.y, w0, acc[1][0]);
                acc[1][1] = fma2(ap0.y, w1, acc[1][1]);
                acc[1][2] = fma2(ap0.y, w2, acc[1][2]);
                acc[1][3] = fma2(ap0.y, w3, acc[1][3]);
                acc[2][0] = fma2(ap1.x, w0, acc[2][0]);
                acc[2][1] = fma2(ap1.x, w1, acc[2][1]);
                acc[2][2] = fma2(ap1.x, w2, acc[2][2]);
                acc[2][3] = fma2(ap1.x, w3, acc[2][3]);
                acc[3][0] = fma2(ap1.y, w0, acc[3][0]);
                acc[3][1] = fma2(ap1.y, w1, acc[3][1]);
                acc[3][2] = fma2(ap1.y, w2, acc[3][2]);
                acc[3][3] = fma2(ap1.y, w3, acc[3][3]);
            }
#pragma unroll
            for (int p = 0; p < 4; p++) {
                float2 c0 = u2f(acc[p][0]);
                float2 c1 = u2f(acc[p][1]);
                float2 c2 = u2f(acc[p][2]);
                float2 c3 = u2f(acc[p][3]);
                int re = rbase + 8 * ty + 2 * p;
                float4 oe; oe.x = c0.x; oe.y = c1.x; oe.z = c2.x; oe.w = c3.x;
                float4 oo; oo.x = c0.y; oo.y = c1.y; oo.z = c2.y; oo.w = c3.y;
                *(float4*)(g_xp + (size_t)re * H_ + 4 * tx)       = oe;
                *(float4*)(g_xp + (size_t)(re + 1) * H_ + 4 * tx) = oo;
            }
        }
    }
}

// ---------------------------------------------------------------------------
// Kernel B: sequential scan, 4-CHAIN PACKED. 128 CTAs x 128 threads,
// exactly ONE CTA per SM (128 < 148), 4 chains per CTA = the unavoidable
// 4-chains-per-busiest-SM, but with tail (MUFU/stores/barrier) amortized
// over 4 chains and h loads shared: hs[k] = float4(c0..c3) -> per chain-step
// 25 LDS + 50 fma2 (vs R7's 25 LDS + 50 fma2 + full tail per 1 chain).
// W row j duplicated-packed in wkd[100] regs. LDG prefetch (no cp.async).
// 4 independent fma2 accumulator chains (depth 50). One barrier per step.
// ---------------------------------------------------------------------------
__global__ void __launch_bounds__(128, 1) scan_kernel(
    const float* __restrict__ noise,   // [B, T, H]
    const float* __restrict__ Wh,      // [H, H]
    const float* __restrict__ ah0,     // [H]
    float* __restrict__ hstore)        // [B, T, H]
{
    __shared__ __align__(16) float4 hs[2][112];   // [buf][k] -> h for chains 0..3

    const int tid  = threadIdx.x;
    const int lane = tid & 31;
    const int w    = tid >> 5;
    const int j    = 25 * w + lane;
    const bool act = lane < 25;
    const int c0   = blockIdx.x * 4;
    const size_t CH = (size_t)T_ * H_;            // chain stride in elements

    // duplicated scaled weights: wkd[k] = (0.1*W[j][k], 0.1*W[j][k])
    ull wkd[100];
    if (act) {
        const float4* wr = (const float4*)(Wh + j * H_);
#pragma unroll
        for (int q = 0; q < 25; q++) {
            float4 v = wr[q];
            wkd[4 * q + 0] = dup2(0.1f * v.x);
            wkd[4 * q + 1] = dup2(0.1f * v.y);
            wkd[4 * q + 2] = dup2(0.1f * v.z);
            wkd[4 * q + 3] = dup2(0.1f * v.w);
        }
    }

    ull ah01 = 0, ah23 = 0;
    if (act) {
        float a0 = ah0[j];
        ah01 = dup2(a0);
        ah23 = ah01;
        float h0 = tanhf(fmaxf(a0, 0.f));
        hs[0][j] = make_float4(h0, h0, h0, h0);
    }

    const float* xpP = g_xp   + (size_t)c0 * CH + j;
    const float* nzP = noise  + (size_t)c0 * CH + j;
    float*       hsP = hstore + (size_t)c0 * CH + j;

    // prefetch t = 0
    float px0 = 0.f, px1 = 0.f, px2 = 0.f, px3 = 0.f;
    float pn0 = 0.f, pn1 = 0.f, pn2 = 0.f, pn3 = 0.f;
    if (act) {
        px0 = xpP[0 * CH]; px1 = xpP[1 * CH]; px2 = xpP[2 * CH]; px3 = xpP[3 * CH];
        pn0 = nzP[0 * CH]; pn1 = nzP[1 * CH]; pn2 = nzP[2 * CH]; pn3 = nzP[3 * CH];
    }
    __syncthreads();

    const ull c09 = dup2(0.9f);
    int buf = 0;
    for (int t = 0; t < T_; t++) {
        if (act) {
            // matvec: 100 LDS.128 + 200 fma2 for 4 chains, 4 indep acc chains
            const ulonglong2* hp = (const ulonglong2*)hs[buf];
            ull a01 = 0, b01 = 0, a23 = 0, b23 = 0;
#pragma unroll
            for (int k2 = 0; k2 < 50; k2++) {
                ulonglong2 v0 = hp[2 * k2];        // k=2k2:   (c0,c1)|(c2,c3)
                ulonglong2 v1 = hp[2 * k2 + 1];    // k=2k2+1
                a01 = fma2(v0.x, wkd[2 * k2],     a01);
                a23 = fma2(v0.y, wkd[2 * k2],     a23);
                b01 = fma2(v1.x, wkd[2 * k2 + 1], b01);
                b23 = fma2(v1.y, wkd[2 * k2 + 1], b23);
            }
            ull m01 = add2(a01, b01);
            ull m23 = add2(a23, b23);

            // ah = 0.9*ah + (m + 0.1*(xp+b))
            ah01 = fma2(c09, ah01, add2(m01, pack2(px0, px1)));
            ah23 = fma2(c09, ah23, add2(m23, pack2(px2, px3)));

            float2 a01f = u2f(ah01);
            float2 a23f = u2f(ah23);
            float xA = fmaxf(a01f.x, 0.f), xB = fmaxf(a01f.y, 0.f);
            float xC = fmaxf(a23f.x, 0.f), xD = fmaxf(a23f.y, 0.f);
            float eA = __expf(-2.f * xA), eB = __expf(-2.f * xB);
            float eC = __expf(-2.f * xC), eD = __expf(-2.f * xD);
            float hA = __fdividef(1.f - eA, 1.f + eA) + pn0;
            float hB = __fdividef(1.f - eB, 1.f + eB) + pn1;
            float hC = __fdividef(1.f - eC, 1.f + eC) + pn2;
            float hD = __fdividef(1.f - eD, 1.f + eD) + pn3;

            hs[buf ^ 1][j] = make_float4(hA, hB, hC, hD);
            size_t ro = (size_t)t * H_;
            hsP[ro + 0 * CH] = hA;
            hsP[ro + 1 * CH] = hB;
            hsP[ro + 2 * CH] = hC;
            hsP[ro + 3 * CH] = hD;

            // prefetch t+1 (px/pn consumed above; ~full next-step latency cover)
            size_t rn = (size_t)((t + 1 < T_) ? (t + 1) : (T_ - 1)) * H_;
            px0 = xpP[rn + 0 * CH]; px1 = xpP[rn + 1 * CH];
            px2 = xpP[rn + 2 * CH]; px3 = xpP[rn + 3 * CH];
            pn0 = nzP[rn + 0 * CH]; pn1 = nzP[rn + 1 * CH];
            pn2 = nzP[rn + 2 * CH]; pn3 = nzP[rn + 3 * CH];
        }
        buf ^= 1;
        __syncthreads();
    }
}

// ---------------------------------------------------------------------------
// Kernel C: output[r][d] = sum_j hstore[r][j] * W_y[d][j]
// ---------------------------------------------------------------------------
__global__ void __launch_bounds__(256) outproj_kernel(
    const float* __restrict__ hst,   // [B*T, H]
    const float* __restrict__ Wy,    // [DO, H]
    float* __restrict__ out)         // [B*T, DO]
{
    __shared__ float wy_s[DO_ * H_];
    const int tid = threadIdx.x;
    for (int idx = tid; idx < DO_ * H_; idx += 256) wy_s[idx] = Wy[idx];
    __syncthreads();

    const int lane = tid & 31;
    const int w    = tid >> 5;
    const size_t row = (size_t)blockIdx.x * 8 + w;

    float a0 = 0.f, a1 = 0.f;
    for (int j = lane; j < H_; j += 32) {
        float h = hst[row * H_ + j];
        a0 = fmaf(h, wy_s[j],      a0);
        a1 = fmaf(h, wy_s[H_ + j], a1);
    }
#pragma unroll
    for (int off = 16; off > 0; off >>= 1) {
        a0 += __shfl_down_sync(0xffffffffu, a0, off);
        a1 += __shfl_down_sync(0xffffffffu, a1, off);
    }
    if (lane == 0) {
        out[row * DO_ + 0] = a0;
        out[row * DO_ + 1] = a1;
    }
}

// ---------------------------------------------------------------------------
extern "C" void kernel_launch(void* const* d_in, const int* in_sizes, int n_in,
                              void* d_out, int out_size)
{
    const float* inp   = (const float*)d_in[0];  // [B,T,DI]
    const float* noise = (const float*)d_in[1];  // [B,T,H]
    const float* Wx    = (const float*)d_in[2];  // [H,DI]
    const float* bias  = (const float*)d_in[3];  // [H]
    const float* Wh    = (const float*)d_in[4];  // [H,H]
    const float* Wy    = (const float*)d_in[5];  // [DO,H]
    const float* ah0   = (const float*)d_in[6];  // [H]

    float* out    = (float*)d_out;                  // [B,T,DO] first
    float* hstore = out + (size_t)B_ * T_ * DO_;    // [B,T,H] second

    const int xp_smem = (DI_ * H_ + DI_ * INS_STRIDE) * (int)sizeof(float);  // 67872 B
    static int attr_done = 0;
    if (!attr_done) {
        cudaFuncSetAttribute(xp_gemm_kernel,
                             cudaFuncAttributeMaxDynamicSharedMemorySize, xp_smem);
        cudaFuncSetAttribute(xp_gemm_kernel,
                             cudaFuncAttributePreferredSharedMemoryCarveout,
                             cudaSharedmemCarveoutMaxShared);
        attr_done = 1;
    }

    xp_gemm_kernel<<<1024, 256, xp_smem>>>(inp, Wx, bias);
    scan_kernel<<<B_ / 4, 128>>>(noise, Wh, ah0, hstore);
    outproj_kernel<<<(B_ * T_) / 8, 256>>>(hstore, Wy, out);
}